// round 1
// baseline (speedup 1.0000x reference)
#include <cuda_runtime.h>
#include <math.h>

// Problem constants
#define Bt   32
#define Ct   684
#define Ht   16
#define Wt   64
#define HWt  1024
#define HIDt 256
#define At   512
#define Kt   11
#define NPATCH 121          // 11*11
#define KCOMB 805           // 684 + 121
#define KPAD  808           // padded to multiple of 8

// Output layout in d_out (tuple order, flattened):
//  [0, 21888)            context_vector [32,684]
//  [21888, 54656)        alpha          [32,16,64]
//  [54656, 87424)        alpha_sum_new  [32,1,16,64]
#define CTX_N   (Bt*Ct)
#define ALPHA_OFF CTX_N
#define ASUM_OFF  (CTX_N + Bt*HWt)

// ---------- scratch (device globals; no allocation allowed) ----------
__device__ float g_query[Bt * At];              // 64 KB
__device__ float g_Wcomb[KPAD * At];            // 1.65 MB, layout [k][a]
__device__ float g_P[Bt * NPATCH * HWt];        // 15.9 MB, im2col patches [b][j][pos]
__device__ float g_Epart[4 * Bt * HWt];         // 512 KB, partial energies per a-tile
__device__ float g_E[Bt * HWt];                 // 128 KB
__device__ float g_bmax[Bt];
__device__ float g_gmax;

// ---------- prep: query = hidden @ Wh^T + bh ----------
__global__ void k_query(const float* __restrict__ hidden,
                        const float* __restrict__ Wh,
                        const float* __restrict__ bh) {
    int b = blockIdx.x, tid = threadIdx.x;
    __shared__ float h[HIDt];
    if (tid < HIDt) h[tid] = hidden[b * HIDt + tid];
    __syncthreads();
    for (int a = tid; a < At; a += 256) {
        const float* wr = Wh + a * HIDt;
        float s = 0.f;
        #pragma unroll 8
        for (int k = 0; k < HIDt; ++k) s = fmaf(wr[k], h[k], s);
        g_query[b * At + a] = s + bh[a];
    }
}

// ---------- prep: Wcomb rows [0,684) = Wec^T ; zero pad rows [805,808) ----------
__global__ void k_tw(const float* __restrict__ Wec) {
    int idx = blockIdx.x * 256 + threadIdx.x;
    const int n1 = Ct * At;
    if (idx < n1) {
        int k = idx / At, a = idx - k * At;
        g_Wcomb[idx] = Wec[a * Ct + k];
    } else if (idx < n1 + 3 * At) {
        g_Wcomb[KCOMB * At + (idx - n1)] = 0.f;
    }
}

// ---------- prep: Wcomb rows [684,805) = Weff^T,  Weff[a,j] = sum_k Waw[a,k]*Wac[k,j] ----------
__global__ void k_weff(const float* __restrict__ Waw,
                       const float* __restrict__ Wac) {
    int a = blockIdx.x, j = threadIdx.x;
    if (j >= NPATCH) return;
    float s = 0.f;
    for (int k = 0; k < At; ++k)
        s = fmaf(Waw[a * At + k], Wac[k * NPATCH + j], s);
    g_Wcomb[(Ct + j) * At + a] = s;
}

// ---------- prep: im2col of alpha_sum (11x11 patches, pad 5) ----------
__global__ void k_patches(const float* __restrict__ asum) {
    int idx = blockIdx.x * 256 + threadIdx.x;
    if (idx >= Bt * NPATCH * HWt) return;
    int pos = idx & (HWt - 1);
    int t = idx >> 10;
    int j = t % NPATCH;
    int b = t / NPATCH;
    int h = pos >> 6, w = pos & 63;
    int hh = h + (j / Kt) - 5;
    int ww = w + (j % Kt) - 5;
    float v = 0.f;
    if (hh >= 0 && hh < Ht && ww >= 0 && ww < Wt)
        v = asum[b * HWt + hh * Wt + ww];
    g_P[idx] = v;
}

// ---------- main fused GEMM + tanh + Wv reduction ----------
// C[pos,a] = sum_k X[k,pos] * Wcomb[k,a]   (both operands K-major: TN layout)
// X rows: k<684 -> cnn[b,k,:,:] (already [k][pos]!), k>=684 -> g_P[b][k-684][:]
// Epilogue: e[pos] += sum over this block's 128 a of Wv[a]*tanh(acc + query[b,a] + bec[a])
__global__ __launch_bounds__(256, 2)
void k_gemm(const float* __restrict__ cnn,
            const float* __restrict__ bec,
            const float* __restrict__ Wv) {
    const int b    = blockIdx.z;
    const int pos0 = blockIdx.x << 7;   // 8 tiles of 128 positions
    const int a0   = blockIdx.y << 7;   // 4 tiles of 128 outputs

    __shared__ float sh[2048];          // Xs[8][128] | Ws[8][128]; reused for reduction
    float* Xs = sh;
    float* Ws = sh + 1024;

    float acc[8][8];
    #pragma unroll
    for (int i = 0; i < 8; ++i)
        #pragma unroll
        for (int j = 0; j < 8; ++j) acc[i][j] = 0.f;

    const int tid   = threadIdx.x;
    const int ldRow = tid >> 5;            // 0..7
    const int ldCol = (tid & 31) << 2;     // 0..124 step 4
    const int tx    = tid & 15;
    const int ty    = tid >> 4;

    const float* Cb = cnn + b * (Ct * HWt);
    const float* Pb = g_P + b * (NPATCH * HWt);

    for (int it = 0; it < 101; ++it) {     // 101*8 = 808 = KPAD
        int kg = (it << 3) + ldRow;
        int kc = kg > (KCOMB - 1) ? (KCOMB - 1) : kg;  // clamp; padded W rows are zero
        const float* xsrc = (kc < Ct) ? (Cb + (kc << 10)) : (Pb + ((kc - Ct) << 10));
        float4 xv = *(const float4*)(xsrc + pos0 + ldCol);
        float4 wv = *(const float4*)(g_Wcomb + (kg << 9) + a0 + ldCol);
        __syncthreads();
        *(float4*)(Xs + (ldRow << 7) + ldCol) = xv;
        *(float4*)(Ws + (ldRow << 7) + ldCol) = wv;
        __syncthreads();
        #pragma unroll
        for (int kk = 0; kk < 8; ++kk) {
            float4 x0 = *(const float4*)(Xs + (kk << 7) + (ty << 2));
            float4 x1 = *(const float4*)(Xs + (kk << 7) + 64 + (ty << 2));
            float4 w0 = *(const float4*)(Ws + (kk << 7) + (tx << 2));
            float4 w1 = *(const float4*)(Ws + (kk << 7) + 64 + (tx << 2));
            float xr[8] = {x0.x, x0.y, x0.z, x0.w, x1.x, x1.y, x1.z, x1.w};
            float wr[8] = {w0.x, w0.y, w0.z, w0.w, w1.x, w1.y, w1.z, w1.w};
            #pragma unroll
            for (int i = 0; i < 8; ++i)
                #pragma unroll
                for (int j = 0; j < 8; ++j)
                    acc[i][j] = fmaf(xr[i], wr[j], acc[i][j]);
        }
    }

    // epilogue: tanh + dot with Wv over this block's 128 a-values
    float e[8];
    #pragma unroll
    for (int i = 0; i < 8; ++i) e[i] = 0.f;
    #pragma unroll
    for (int j = 0; j < 8; ++j) {
        int aj = a0 + ((j < 4) ? ((tx << 2) + j) : (64 + (tx << 2) + j - 4));
        float qb  = g_query[(b << 9) + aj] + bec[aj];
        float wvv = Wv[aj];
        #pragma unroll
        for (int i = 0; i < 8; ++i)
            e[i] = fmaf(wvv, tanhf(acc[i][j] + qb), e[i]);
    }

    __syncthreads();
    #pragma unroll
    for (int i = 0; i < 8; ++i) {
        int pl = (i < 4) ? ((ty << 2) + i) : (64 + (ty << 2) + i - 4);
        sh[(pl << 4) + tx] = e[i];        // red[128][16]
    }
    __syncthreads();
    if (tid < 128) {
        float s = 0.f;
        #pragma unroll
        for (int t = 0; t < 16; ++t) s += sh[(tid << 4) + t];
        g_Epart[blockIdx.y * (Bt * HWt) + (b << 10) + pos0 + tid] = s;
    }
}

// ---------- reduce 4 a-tile partials, add bv, per-b max ----------
__global__ void k_reduceE(const float* __restrict__ bv) {
    int b = blockIdx.x, tid = threadIdx.x;
    float bvv = bv[0];
    float m = -1e30f;
    for (int p = tid; p < HWt; p += 256) {
        float s = bvv;
        #pragma unroll
        for (int t = 0; t < 4; ++t) s += g_Epart[t * (Bt * HWt) + b * HWt + p];
        g_E[b * HWt + p] = s;
        m = fmaxf(m, s);
    }
    __shared__ float sm[256];
    sm[tid] = m;
    __syncthreads();
    for (int s2 = 128; s2 > 0; s2 >>= 1) {
        if (tid < s2) sm[tid] = fmaxf(sm[tid], sm[tid + s2]);
        __syncthreads();
    }
    if (tid == 0) g_bmax[b] = sm[0];
}

// ---------- global max over 32 per-b maxes ----------
__global__ void k_gmax() {
    float v = g_bmax[threadIdx.x];
    #pragma unroll
    for (int o = 16; o > 0; o >>= 1) v = fmaxf(v, __shfl_xor_sync(0xffffffffu, v, o));
    if (threadIdx.x == 0) g_gmax = v;
}

// ---------- per-b softmax; write alpha and alpha_sum_new ----------
__global__ void k_softmax(const float* __restrict__ mask,
                          const float* __restrict__ asum,
                          float* __restrict__ out) {
    int b = blockIdx.x, tid = threadIdx.x;
    __shared__ float ex[HWt];
    __shared__ float sm[256];
    float gm = g_gmax;
    float ls = 0.f;
    for (int p = tid; p < HWt; p += 256) {
        float v = expf(g_E[b * HWt + p] - gm) * mask[b * HWt + p];
        ex[p] = v;
        ls += v;
    }
    sm[tid] = ls;
    __syncthreads();
    for (int s2 = 128; s2 > 0; s2 >>= 1) {
        if (tid < s2) sm[tid] += sm[tid + s2];
        __syncthreads();
    }
    float inv = 1.f / (sm[0] + 1e-10f);
    for (int p = tid; p < HWt; p += 256) {
        float al = ex[p] * inv;
        out[ALPHA_OFF + b * HWt + p] = al;
        out[ASUM_OFF  + b * HWt + p] = al + asum[b * HWt + p];
    }
}

// ---------- context[b,c] = sum_pos alpha[b,pos] * cnn[b,c,pos] ----------
__global__ void k_context(const float* __restrict__ cnn,
                          float* __restrict__ out) {
    int c = blockIdx.x, b = blockIdx.y, tid = threadIdx.x;
    const float* f  = cnn + (b * Ct + c) * HWt;
    const float* al = out + ALPHA_OFF + b * HWt;
    float s = 0.f;
    for (int p = tid; p < HWt; p += 128) s = fmaf(al[p], f[p], s);
    #pragma unroll
    for (int o = 16; o > 0; o >>= 1) s += __shfl_xor_sync(0xffffffffu, s, o);
    __shared__ float sm[4];
    if ((tid & 31) == 0) sm[tid >> 5] = s;
    __syncthreads();
    if (tid == 0) out[b * Ct + c] = sm[0] + sm[1] + sm[2] + sm[3];
}

// ---------- launch ----------
extern "C" void kernel_launch(void* const* d_in, const int* in_sizes, int n_in,
                              void* d_out, int out_size) {
    const float* cnn    = (const float*)d_in[0];
    const float* hidden = (const float*)d_in[1];
    const float* asum   = (const float*)d_in[2];
    const float* mask   = (const float*)d_in[3];
    const float* Wh     = (const float*)d_in[4];
    const float* bh     = (const float*)d_in[5];
    const float* Wec    = (const float*)d_in[6];
    const float* bec    = (const float*)d_in[7];
    const float* Wac    = (const float*)d_in[8];
    const float* Waw    = (const float*)d_in[9];
    const float* Wv     = (const float*)d_in[10];
    const float* bv     = (const float*)d_in[11];
    float* out = (float*)d_out;

    k_query<<<Bt, 256>>>(hidden, Wh, bh);
    {
        int ntw = Ct * At + 3 * At;
        k_tw<<<(ntw + 255) / 256, 256>>>(Wec);
    }
    k_weff<<<At, 128>>>(Waw, Wac);
    k_patches<<<(Bt * NPATCH * HWt + 255) / 256, 256>>>(asum);
    k_gemm<<<dim3(HWt / 128, At / 128, Bt), 256>>>(cnn, bec, Wv);
    k_reduceE<<<Bt, 256>>>(bv);
    k_gmax<<<1, 32>>>();
    k_softmax<<<Bt, 256>>>(mask, asum, out);
    k_context<<<dim3(Ct, Bt), 128>>>(cnn, out);
}